// round 3
// baseline (speedup 1.0000x reference)
#include <cuda_runtime.h>
#include <cuda_bf16.h>
#include <mma.h>
#include <cstdint>

using namespace nvcuda;

#define SQ   2048
#define BB   8
#define DD   512
#define HH   8
#define HDIM 64
#define MROWS (SQ*BB)       // 16384
#define NQKV  (3*DD)        // 1536
#define BH    (BB*HH)       // 64

// ---------------- scratch (__device__ globals; no allocs allowed) ----------
__device__ __nv_bfloat16 g_qhi[(size_t)BH*SQ*HDIM];   // [bh][s][hd], pre-scaled
__device__ __nv_bfloat16 g_qlo[(size_t)BH*SQ*HDIM];
__device__ __nv_bfloat16 g_khi[(size_t)BH*SQ*HDIM];   // [bh][t][hd]
__device__ __nv_bfloat16 g_klo[(size_t)BH*SQ*HDIM];
__device__ __nv_bfloat16 g_vhi[(size_t)BH*SQ*HDIM];   // [bh][t][hd]
__device__ __nv_bfloat16 g_vlo[(size_t)BH*SQ*HDIM];
__device__ float g_scores[(size_t)BH*SQ*SQ];          // raw (pre-exp) scores, 1GB
__device__ float g_rowinv[(size_t)BH*SQ];             // 1 / sum(exp(row))
__device__ float g_ctx[(size_t)MROWS*DD];             // [s][b][d]

__device__ __forceinline__ void split2(float x0, float x1, uint32_t& hi, uint32_t& lo) {
    __nv_bfloat16 h0 = __float2bfloat16(x0), h1 = __float2bfloat16(x1);
    float r0 = x0 - __bfloat162float(h0), r1 = x1 - __bfloat162float(h1);
    __nv_bfloat162 H = __halves2bfloat162(h0, h1);
    __nv_bfloat162 L = __halves2bfloat162(__float2bfloat16(r0), __float2bfloat16(r1));
    hi = *(uint32_t*)&H;
    lo = *(uint32_t*)&L;
}

// ---------------------------------------------------------------------------
// K1: QKV projection (scalar fp32). Emits split-bf16 Q/K/V in [bh][s|t][hd].
// ---------------------------------------------------------------------------
__global__ void qkv_gemm(const float* __restrict__ A, const float* __restrict__ W,
                         const float* __restrict__ bias) {
    __shared__ float As[64][17];
    __shared__ float Ws[64][17];
    int tx = threadIdx.x, ty = threadIdx.y;
    int tid = ty * 16 + tx;
    int m0 = blockIdx.y * 64;
    int n0 = blockIdx.x * 64;
    float acc[4][4] = {};
    for (int k0 = 0; k0 < DD; k0 += 16) {
        #pragma unroll
        for (int l = 0; l < 4; l++) {
            int idx = tid + l * 256;
            int r = idx >> 4, c = idx & 15;
            As[r][c] = A[(size_t)(m0 + r) * DD + k0 + c];
            Ws[r][c] = W[(size_t)(n0 + r) * DD + k0 + c];
        }
        __syncthreads();
        #pragma unroll
        for (int kk = 0; kk < 16; kk++) {
            float a[4], b[4];
            #pragma unroll
            for (int r = 0; r < 4; r++) a[r] = As[ty * 4 + r][kk];
            #pragma unroll
            for (int c = 0; c < 4; c++) b[c] = Ws[tx * 4 + c][kk];
            #pragma unroll
            for (int r = 0; r < 4; r++)
                #pragma unroll
                for (int c = 0; c < 4; c++)
                    acc[r][c] += a[r] * b[c];
        }
        __syncthreads();
    }
    int part = n0 >> 9;            // 0=q, 1=k, 2=v (64-wide tile never crosses)
    int h    = (n0 >> 6) & 7;      // head
    __nv_bfloat16* ph = (part == 0) ? g_qhi : (part == 1) ? g_khi : g_vhi;
    __nv_bfloat16* pl = (part == 0) ? g_qlo : (part == 1) ? g_klo : g_vlo;
    float scale = (part == 0) ? 0.125f : 1.0f;
    #pragma unroll
    for (int r = 0; r < 4; r++) {
        int i = m0 + ty * 4 + r;
        int s = i / BB, b = i % BB;
        int bh = b * HH + h;
        float v[4];
        #pragma unroll
        for (int c = 0; c < 4; c++) v[c] = (acc[r][c] + bias[n0 + tx * 4 + c]) * scale;
        uint32_t h0, l0, h1, l1;
        split2(v[0], v[1], h0, l0);
        split2(v[2], v[3], h1, l1);
        size_t off = ((size_t)bh * SQ + s) * HDIM + tx * 4;
        *(uint32_t*)(ph + off)     = h0;
        *(uint32_t*)(ph + off + 2) = h1;
        *(uint32_t*)(pl + off)     = l0;
        *(uint32_t*)(pl + off + 2) = l1;
    }
}

// ---------------------------------------------------------------------------
// K2: scores = Q.K^T via WMMA bf16 split (3 products). CTA tile 64(s)x128(t).
// smem: Q 64x64 hi/lo (16KB) + K 128x64 hi/lo (32KB) = 48KB.
// ---------------------------------------------------------------------------
__global__ void __launch_bounds__(256) scores_wmma() {
    __shared__ __nv_bfloat16 Qh[64 * 64];
    __shared__ __nv_bfloat16 Ql[64 * 64];
    __shared__ __nv_bfloat16 Kh[128 * 64];
    __shared__ __nv_bfloat16 Kl[128 * 64];

    int tid = threadIdx.x;
    int wid = tid >> 5;
    int bh = blockIdx.z;
    int s0 = blockIdx.y * 64;
    int t0 = blockIdx.x * 128;

    // load Q tile (512 uint4 per matrix)
    {
        const uint4* sh = (const uint4*)(g_qhi + ((size_t)bh * SQ + s0) * HDIM);
        const uint4* sl = (const uint4*)(g_qlo + ((size_t)bh * SQ + s0) * HDIM);
        #pragma unroll
        for (int l = 0; l < 2; l++) {
            int idx = tid + l * 256;
            ((uint4*)Qh)[idx] = sh[idx];
            ((uint4*)Ql)[idx] = sl[idx];
        }
        const uint4* th = (const uint4*)(g_khi + ((size_t)bh * SQ + t0) * HDIM);
        const uint4* tl = (const uint4*)(g_klo + ((size_t)bh * SQ + t0) * HDIM);
        #pragma unroll
        for (int l = 0; l < 4; l++) {
            int idx = tid + l * 256;
            ((uint4*)Kh)[idx] = th[idx];
            ((uint4*)Kl)[idx] = tl[idx];
        }
    }
    __syncthreads();

    int wy = wid & 1;    // 0..1 : 32-row group
    int wx = wid >> 1;   // 0..3 : 32-col group

    wmma::fragment<wmma::accumulator, 16, 16, 16, float> acc[2][2];
    #pragma unroll
    for (int i = 0; i < 2; i++)
        #pragma unroll
        for (int j = 0; j < 2; j++)
            wmma::fill_fragment(acc[i][j], 0.0f);

    const __nv_bfloat16* aSrc[3] = { Qh, Qh, Ql };
    const __nv_bfloat16* bSrc[3] = { Kh, Kl, Kh };
    #pragma unroll
    for (int p = 0; p < 3; p++) {
        #pragma unroll
        for (int k = 0; k < 4; k++) {
            wmma::fragment<wmma::matrix_a, 16, 16, 16, __nv_bfloat16, wmma::row_major> a[2];
            wmma::fragment<wmma::matrix_b, 16, 16, 16, __nv_bfloat16, wmma::col_major> b[2];
            #pragma unroll
            for (int i = 0; i < 2; i++)
                wmma::load_matrix_sync(a[i], aSrc[p] + (wy * 32 + i * 16) * 64 + k * 16, 64);
            #pragma unroll
            for (int j = 0; j < 2; j++)
                wmma::load_matrix_sync(b[j], bSrc[p] + (wx * 32 + j * 16) * 64 + k * 16, 64);
            #pragma unroll
            for (int i = 0; i < 2; i++)
                #pragma unroll
                for (int j = 0; j < 2; j++)
                    wmma::mma_sync(acc[i][j], a[i], b[j], acc[i][j]);
        }
    }

    float* out = g_scores + ((size_t)bh * SQ + s0) * SQ + t0;
    #pragma unroll
    for (int i = 0; i < 2; i++)
        #pragma unroll
        for (int j = 0; j < 2; j++)
            wmma::store_matrix_sync(out + (size_t)(wy * 32 + i * 16) * SQ + wx * 32 + j * 16,
                                    acc[i][j], SQ, wmma::mem_row_major);
}

// ---------------------------------------------------------------------------
// K3: ctx = softmax(scores) @ V via WMMA bf16 split, exp+rowsum fused.
// CTA: 64 s-rows x 64 d, K=2048 swept in 64-chunks.
// ---------------------------------------------------------------------------
__global__ void __launch_bounds__(256) ctx_wmma() {
    __shared__ __nv_bfloat16 Ph[64 * 64];    // 8KB  (aliased as outS after loop)
    __shared__ __nv_bfloat16 Pl[64 * 64];    // 8KB
    __shared__ __nv_bfloat16 Vh[64 * 64];
    __shared__ __nv_bfloat16 Vl[64 * 64];
    __shared__ float rs[256];
    __shared__ float invS[64];

    int tid = threadIdx.x;
    int wid = tid >> 5;
    int bh = blockIdx.y;
    int s0 = blockIdx.x * 64;

    int row = tid >> 2;          // 0..63
    int seg = tid & 3;           // 0..3  (16 cols each)

    int wy = wid & 3;            // 0..3 : 16-row group
    int wx = wid >> 2;           // 0..1 : 32-col group

    wmma::fragment<wmma::accumulator, 16, 16, 16, float> acc[2];
    wmma::fill_fragment(acc[0], 0.0f);
    wmma::fill_fragment(acc[1], 0.0f);

    const float* prow = g_scores + ((size_t)bh * SQ + s0 + row) * SQ + seg * 16;
    const uint4* vh = (const uint4*)(g_vhi + (size_t)bh * SQ * HDIM);
    const uint4* vl = (const uint4*)(g_vlo + (size_t)bh * SQ * HDIM);

    float rowsum = 0.0f;
    for (int c = 0; c < 32; c++) {
        // exp + split P chunk into smem
        const float4* p4 = (const float4*)(prow + c * 64);
        #pragma unroll
        for (int j = 0; j < 4; j++) {
            float4 v = p4[j];
            float e0 = __expf(v.x), e1 = __expf(v.y), e2 = __expf(v.z), e3 = __expf(v.w);
            rowsum += (e0 + e1) + (e2 + e3);
            uint32_t h01, l01, h23, l23;
            split2(e0, e1, h01, l01);
            split2(e2, e3, h23, l23);
            uint32_t off = row * 64 + seg * 16 + j * 4;
            *(uint2*)(Ph + off) = make_uint2(h01, h23);
            *(uint2*)(Pl + off) = make_uint2(l01, l23);
        }
        // V chunk -> smem (512 uint4 per matrix)
        #pragma unroll
        for (int l = 0; l < 2; l++) {
            int idx = tid + l * 256;
            ((uint4*)Vh)[idx] = vh[c * 512 + idx];
            ((uint4*)Vl)[idx] = vl[c * 512 + idx];
        }
        __syncthreads();

        const __nv_bfloat16* aSrc[3] = { Ph, Ph, Pl };
        const __nv_bfloat16* bSrc[3] = { Vh, Vl, Vh };
        #pragma unroll
        for (int p = 0; p < 3; p++) {
            #pragma unroll
            for (int k = 0; k < 4; k++) {
                wmma::fragment<wmma::matrix_a, 16, 16, 16, __nv_bfloat16, wmma::row_major> a;
                wmma::load_matrix_sync(a, aSrc[p] + (wy * 16) * 64 + k * 16, 64);
                #pragma unroll
                for (int j = 0; j < 2; j++) {
                    wmma::fragment<wmma::matrix_b, 16, 16, 16, __nv_bfloat16, wmma::row_major> b;
                    wmma::load_matrix_sync(b, bSrc[p] + (k * 16) * 64 + wx * 32 + j * 16, 64);
                    wmma::mma_sync(acc[j], a, b, acc[j]);
                }
            }
        }
        __syncthreads();
    }

    // row sums -> inv
    rs[tid] = rowsum;
    __syncthreads();
    if (seg == 0) {
        float s = rs[row * 4] + rs[row * 4 + 1] + rs[row * 4 + 2] + rs[row * 4 + 3];
        float inv = 1.0f / s;
        invS[row] = inv;
        g_rowinv[(size_t)bh * SQ + s0 + row] = inv;
    }

    // stage acc into smem (alias Ph/Pl region as 64x64 f32 = 16KB)
    float* outS = (float*)Ph;
    __syncthreads();
    #pragma unroll
    for (int j = 0; j < 2; j++)
        wmma::store_matrix_sync(outS + (wy * 16) * 64 + wx * 32 + j * 16, acc[j], 64,
                                wmma::mem_row_major);
    __syncthreads();

    int b = bh >> 3, h = bh & 7;
    float inv = invS[row];
    float* orow = g_ctx + ((size_t)(s0 + row) * BB + b) * DD + h * HDIM + seg * 16;
    #pragma unroll
    for (int j = 0; j < 4; j++) {
        float4 v = *(float4*)(outS + row * 64 + seg * 16 + j * 4);
        *(float4*)(orow + j * 4) = make_float4(v.x * inv, v.y * inv, v.z * inv, v.w * inv);
    }
}

// ---------------------------------------------------------------------------
// K4: attn_weights[b,s,t] = mean_h exp(scores) * rowinv
// ---------------------------------------------------------------------------
__global__ void head_avg(float* __restrict__ out_attn) {
    size_t i = (size_t)blockIdx.x * blockDim.x + threadIdx.x;
    if (i >= (size_t)BB * SQ * SQ) return;
    size_t b   = i / ((size_t)SQ * SQ);
    size_t rem = i % ((size_t)SQ * SQ);
    size_t s   = rem / SQ;
    float sum = 0.0f;
    #pragma unroll
    for (int h = 0; h < HH; h++) {
        size_t bh = b * HH + h;
        sum += __expf(g_scores[bh * SQ * SQ + rem]) * g_rowinv[bh * SQ + s];
    }
    out_attn[i] = sum * 0.125f;
}

// ---------------------------------------------------------------------------
// K5: out = ctx @ out_w^T + out_b  (scalar fp32)
// ---------------------------------------------------------------------------
__global__ void out_gemm(const float* __restrict__ W, const float* __restrict__ bias,
                         float* __restrict__ out) {
    __shared__ float As[64][17];
    __shared__ float Ws[64][17];
    int tx = threadIdx.x, ty = threadIdx.y;
    int tid = ty * 16 + tx;
    int m0 = blockIdx.y * 64;
    int n0 = blockIdx.x * 64;
    float acc[4][4] = {};
    for (int k0 = 0; k0 < DD; k0 += 16) {
        #pragma unroll
        for (int l = 0; l < 4; l++) {
            int idx = tid + l * 256;
            int r = idx >> 4, c = idx & 15;
            As[r][c] = g_ctx[(size_t)(m0 + r) * DD + k0 + c];
            Ws[r][c] = W[(size_t)(n0 + r) * DD + k0 + c];
        }
        __syncthreads();
        #pragma unroll
        for (int kk = 0; kk < 16; kk++) {
            float a[4], b[4];
            #pragma unroll
            for (int r = 0; r < 4; r++) a[r] = As[ty * 4 + r][kk];
            #pragma unroll
            for (int c = 0; c < 4; c++) b[c] = Ws[tx * 4 + c][kk];
            #pragma unroll
            for (int r = 0; r < 4; r++)
                #pragma unroll
                for (int c = 0; c < 4; c++)
                    acc[r][c] += a[r] * b[c];
        }
        __syncthreads();
    }
    #pragma unroll
    for (int r = 0; r < 4; r++) {
        int i = m0 + ty * 4 + r;
        #pragma unroll
        for (int c = 0; c < 4; c++) {
            int j = n0 + tx * 4 + c;
            out[(size_t)i * DD + j] = acc[r][c] + bias[j];
        }
    }
}

extern "C" void kernel_launch(void* const* d_in, const int* in_sizes, int n_in,
                              void* d_out, int out_size) {
    const float* src   = (const float*)d_in[0];
    const float* in_w  = (const float*)d_in[1];
    const float* in_b  = (const float*)d_in[2];
    const float* out_w = (const float*)d_in[3];
    const float* out_b = (const float*)d_in[4];
    float* out      = (float*)d_out;
    float* attn_out = out + (size_t)SQ * BB * DD;

    dim3 thr(16, 16);
    qkv_gemm<<<dim3(NQKV / 64, MROWS / 64), thr>>>(src, in_w, in_b);
    scores_wmma<<<dim3(SQ / 128, SQ / 64, BH), 256>>>();
    ctx_wmma<<<dim3(SQ / 64, BH), 256>>>();
    head_avg<<<(unsigned)(((size_t)BB * SQ * SQ + 255) / 256), 256>>>(attn_out);
    out_gemm<<<dim3(DD / 64, MROWS / 64), thr>>>(out_w, out_b, out);
}

// round 5
// speedup vs baseline: 2.3138x; 2.3138x over previous
#include <cuda_runtime.h>
#include <cuda_bf16.h>
#include <mma.h>
#include <cstdint>

using namespace nvcuda;

#define SQ   2048
#define BB   8
#define DD   512
#define HH   8
#define HDIM 64
#define MROWS (SQ*BB)       // 16384
#define BH    (BB*HH)       // 64

// ---------------- scratch (__device__ globals) -----------------------------
__device__ __nv_bfloat16 g_shi[(size_t)MROWS*DD];     // split src
__device__ __nv_bfloat16 g_slo[(size_t)MROWS*DD];
__device__ __nv_bfloat16 g_wihi[(size_t)3*DD*DD];     // split in_proj_w
__device__ __nv_bfloat16 g_wilo[(size_t)3*DD*DD];
__device__ __nv_bfloat16 g_wohi[(size_t)DD*DD];       // split out_w
__device__ __nv_bfloat16 g_wolo[(size_t)DD*DD];
__device__ __nv_bfloat16 g_qhi[(size_t)BH*SQ*HDIM];   // [bh][s][hd], pre-scaled
__device__ __nv_bfloat16 g_qlo[(size_t)BH*SQ*HDIM];
__device__ __nv_bfloat16 g_khi[(size_t)BH*SQ*HDIM];   // [bh][t][hd]
__device__ __nv_bfloat16 g_klo[(size_t)BH*SQ*HDIM];
__device__ __nv_bfloat16 g_vhi[(size_t)BH*SQ*HDIM];   // [bh][t][hd]
__device__ __nv_bfloat16 g_vlo[(size_t)BH*SQ*HDIM];
__device__ float g_scores[(size_t)BH*SQ*SQ];          // raw pre-exp scores (1GB)
__device__ float g_rowinv[(size_t)BH*SQ];
__device__ __nv_bfloat16 g_cthi[(size_t)MROWS*DD];    // split ctx [m][col]
__device__ __nv_bfloat16 g_ctlo[(size_t)MROWS*DD];

__device__ __forceinline__ void split2(float x0, float x1, uint32_t& hi, uint32_t& lo) {
    __nv_bfloat16 h0 = __float2bfloat16(x0), h1 = __float2bfloat16(x1);
    float r0 = x0 - __bfloat162float(h0), r1 = x1 - __bfloat162float(h1);
    __nv_bfloat162 H = __halves2bfloat162(h0, h1);
    __nv_bfloat162 L = __halves2bfloat162(__float2bfloat16(r0), __float2bfloat16(r1));
    hi = *(uint32_t*)&H;
    lo = *(uint32_t*)&L;
}

// ---------------------------------------------------------------------------
// K0: elementwise fp32 -> split bf16 (hi/lo), 4 elements per thread
// ---------------------------------------------------------------------------
__global__ void split_f32(const float* __restrict__ in, __nv_bfloat16* __restrict__ hi,
                          __nv_bfloat16* __restrict__ lo, int n4) {
    int i = blockIdx.x * blockDim.x + threadIdx.x;
    if (i >= n4) return;
    float4 v = ((const float4*)in)[i];
    uint32_t h01, l01, h23, l23;
    split2(v.x, v.y, h01, l01);
    split2(v.z, v.w, h23, l23);
    ((uint2*)hi)[i] = make_uint2(h01, h23);
    ((uint2*)lo)[i] = make_uint2(l01, l23);
}

// ---------------------------------------------------------------------------
// K1: QKV projection, split-bf16 3-product WMMA. CTA 128(m) x 64(n), K=512.
// Scatters q/k/v (all split) into [bh][s][hd].
// ---------------------------------------------------------------------------
__global__ void __launch_bounds__(256) qkv_wmma(const float* __restrict__ bias) {
    __shared__ __align__(16) unsigned char smraw[34816];
    __nv_bfloat16* Ah = (__nv_bfloat16*)smraw;                 // 128*40
    __nv_bfloat16* Al = Ah + 128 * 40;
    __nv_bfloat16* Bh = Al + 128 * 40;                         // 64*40
    __nv_bfloat16* Bl = Bh + 64 * 40;
    float* stage = (float*)smraw;                              // 128*68

    int tid = threadIdx.x;
    int wid = tid >> 5;
    int wy = wid & 3, wx = wid >> 2;
    int n0 = blockIdx.x * 64, m0 = blockIdx.y * 128;

    wmma::fragment<wmma::accumulator, 16, 16, 16, float> acc[2][2];
    #pragma unroll
    for (int i = 0; i < 2; i++)
        #pragma unroll
        for (int j = 0; j < 2; j++) wmma::fill_fragment(acc[i][j], 0.0f);

    for (int k0 = 0; k0 < DD; k0 += 32) {
        #pragma unroll
        for (int l = 0; l < 2; l++) {
            int idx = tid + l * 256;
            int r = idx >> 2, c = idx & 3;
            *(uint4*)&Ah[r * 40 + c * 8] = *(const uint4*)&g_shi[(size_t)(m0 + r) * DD + k0 + c * 8];
            *(uint4*)&Al[r * 40 + c * 8] = *(const uint4*)&g_slo[(size_t)(m0 + r) * DD + k0 + c * 8];
        }
        {
            int r = tid >> 2, c = tid & 3;
            *(uint4*)&Bh[r * 40 + c * 8] = *(const uint4*)&g_wihi[(size_t)(n0 + r) * DD + k0 + c * 8];
            *(uint4*)&Bl[r * 40 + c * 8] = *(const uint4*)&g_wilo[(size_t)(n0 + r) * DD + k0 + c * 8];
        }
        __syncthreads();
        #pragma unroll
        for (int p = 0; p < 3; p++) {
            const __nv_bfloat16* aS = (p == 2) ? Al : Ah;
            const __nv_bfloat16* bS = (p == 1) ? Bl : Bh;
            #pragma unroll
            for (int kk = 0; kk < 2; kk++) {
                wmma::fragment<wmma::matrix_a, 16, 16, 16, __nv_bfloat16, wmma::row_major> a[2];
                wmma::fragment<wmma::matrix_b, 16, 16, 16, __nv_bfloat16, wmma::col_major> b[2];
                #pragma unroll
                for (int i = 0; i < 2; i++)
                    wmma::load_matrix_sync(a[i], aS + (wy * 32 + i * 16) * 40 + kk * 16, 40);
                #pragma unroll
                for (int j = 0; j < 2; j++)
                    wmma::load_matrix_sync(b[j], bS + (wx * 32 + j * 16) * 40 + kk * 16, 40);
                #pragma unroll
                for (int i = 0; i < 2; i++)
                    #pragma unroll
                    for (int j = 0; j < 2; j++)
                        wmma::mma_sync(acc[i][j], a[i], b[j], acc[i][j]);
            }
        }
        __syncthreads();
    }
    #pragma unroll
    for (int i = 0; i < 2; i++)
        #pragma unroll
        for (int j = 0; j < 2; j++)
            wmma::store_matrix_sync(stage + (wy * 32 + i * 16) * 68 + wx * 32 + j * 16,
                                    acc[i][j], 68, wmma::mem_row_major);
    __syncthreads();

    int row = tid >> 1, half = (tid & 1) * 32;
    int part = n0 >> 9;           // 0=q 1=k 2=v
    int h = (n0 >> 6) & 7;
    int i = m0 + row;
    int s = i >> 3, b = i & 7;
    int bh = b * HH + h;
    float scale = (part == 0) ? 0.125f : 1.0f;
    size_t obase = ((size_t)bh * SQ + s) * HDIM + half;
    __nv_bfloat16* ph = (part == 0) ? g_qhi : (part == 1) ? g_khi : g_vhi;
    __nv_bfloat16* pl = (part == 0) ? g_qlo : (part == 1) ? g_klo : g_vlo;
    #pragma unroll
    for (int j = 0; j < 8; j++) {
        float4 v = *(float4*)&stage[row * 68 + half + j * 4];
        int col = n0 + half + j * 4;
        v.x = (v.x + bias[col]) * scale;
        v.y = (v.y + bias[col + 1]) * scale;
        v.z = (v.z + bias[col + 2]) * scale;
        v.w = (v.w + bias[col + 3]) * scale;
        uint32_t h01, l01, h23, l23;
        split2(v.x, v.y, h01, l01);
        split2(v.z, v.w, h23, l23);
        *(uint2*)(ph + obase + j * 4) = make_uint2(h01, h23);
        *(uint2*)(pl + obase + j * 4) = make_uint2(l01, l23);
    }
}

// ---------------------------------------------------------------------------
// K2: scores = Q.K^T, split-bf16 3-product WMMA. CTA 64(s) x 64(t), K=64.
// ---------------------------------------------------------------------------
__global__ void __launch_bounds__(256) scores_wmma() {
    __shared__ __nv_bfloat16 Qh[64 * 72];
    __shared__ __nv_bfloat16 Ql[64 * 72];
    __shared__ __nv_bfloat16 Kh[64 * 72];
    __shared__ __nv_bfloat16 Kl[64 * 72];

    int tid = threadIdx.x;
    int wid = tid >> 5;
    int wy = wid & 3, wx = wid >> 2;
    int bh = blockIdx.z;
    int s0 = blockIdx.y * 64;
    int t0 = blockIdx.x * 64;

    #pragma unroll
    for (int l = 0; l < 2; l++) {
        int idx = tid + l * 256;
        int r = idx >> 3, c = idx & 7;
        *(uint4*)&Qh[r * 72 + c * 8] = *(const uint4*)&g_qhi[((size_t)bh * SQ + s0 + r) * HDIM + c * 8];
        *(uint4*)&Ql[r * 72 + c * 8] = *(const uint4*)&g_qlo[((size_t)bh * SQ + s0 + r) * HDIM + c * 8];
        *(uint4*)&Kh[r * 72 + c * 8] = *(const uint4*)&g_khi[((size_t)bh * SQ + t0 + r) * HDIM + c * 8];
        *(uint4*)&Kl[r * 72 + c * 8] = *(const uint4*)&g_klo[((size_t)bh * SQ + t0 + r) * HDIM + c * 8];
    }
    __syncthreads();

    wmma::fragment<wmma::accumulator, 16, 16, 16, float> acc[2];
    wmma::fill_fragment(acc[0], 0.0f);
    wmma::fill_fragment(acc[1], 0.0f);

    #pragma unroll
    for (int p = 0; p < 3; p++) {
        const __nv_bfloat16* aS = (p == 2) ? Ql : Qh;
        const __nv_bfloat16* bS = (p == 1) ? Kl : Kh;
        #pragma unroll
        for (int kk = 0; kk < 4; kk++) {
            wmma::fragment<wmma::matrix_a, 16, 16, 16, __nv_bfloat16, wmma::row_major> a;
            wmma::load_matrix_sync(a, aS + (wy * 16) * 72 + kk * 16, 72);
            #pragma unroll
            for (int j = 0; j < 2; j++) {
                wmma::fragment<wmma::matrix_b, 16, 16, 16, __nv_bfloat16, wmma::col_major> b;
                wmma::load_matrix_sync(b, bS + (wx * 32 + j * 16) * 72 + kk * 16, 72);
                wmma::mma_sync(acc[j], a, b, acc[j]);
            }
        }
    }
    float* out = g_scores + ((size_t)bh * SQ + s0 + wy * 16) * SQ + t0 + wx * 32;
    wmma::store_matrix_sync(out, acc[0], SQ, wmma::mem_row_major);
    wmma::store_matrix_sync(out + 16, acc[1], SQ, wmma::mem_row_major);
}

// ---------------------------------------------------------------------------
// K3: ctx = exp(scores) @ V, split-bf16 3-product WMMA; rowsum fused.
// CTA 64(s) x 64(d), K=2048 in 64-chunks. Emits split-bf16 ctx + rowinv.
// ---------------------------------------------------------------------------
__global__ void __launch_bounds__(256) ctx_wmma() {
    __shared__ __align__(16) unsigned char smraw[36864];
    __nv_bfloat16* Ph = (__nv_bfloat16*)smraw;    // 64*72 each
    __nv_bfloat16* Pl = Ph + 64 * 72;
    __nv_bfloat16* Vh = Pl + 64 * 72;
    __nv_bfloat16* Vl = Vh + 64 * 72;
    float* stage = (float*)smraw;                 // 64*68 f32

    int tid = threadIdx.x;
    int wid = tid >> 5;
    int wy = wid & 3, wx = wid >> 2;
    int bh = blockIdx.y;
    int s0 = blockIdx.x * 64;

    int row = tid >> 2, seg = (tid & 3) * 16;
    const float* prow = g_scores + ((size_t)bh * SQ + s0 + row) * SQ + seg;

    wmma::fragment<wmma::accumulator, 16, 16, 16, float> acc[2];
    wmma::fill_fragment(acc[0], 0.0f);
    wmma::fill_fragment(acc[1], 0.0f);

    float rowsum = 0.0f;
    for (int c = 0; c < 32; c++) {
        #pragma unroll
        for (int j = 0; j < 4; j++) {
            float4 v = *(const float4*)&prow[c * 64 + j * 4];
            float e0 = __expf(v.x), e1 = __expf(v.y), e2 = __expf(v.z), e3 = __expf(v.w);
            rowsum += (e0 + e1) + (e2 + e3);
            uint32_t h01, l01, h23, l23;
            split2(e0, e1, h01, l01);
            split2(e2, e3, h23, l23);
            *(uint2*)&Ph[row * 72 + seg + j * 4] = make_uint2(h01, h23);
            *(uint2*)&Pl[row * 72 + seg + j * 4] = make_uint2(l01, l23);
        }
        #pragma unroll
        for (int l = 0; l < 2; l++) {
            int idx = tid + l * 256;
            int r = idx >> 3, c8 = idx & 7;
            size_t goff = ((size_t)bh * SQ + c * 64 + r) * HDIM + c8 * 8;
            *(uint4*)&Vh[r * 72 + c8 * 8] = *(const uint4*)&g_vhi[goff];
            *(uint4*)&Vl[r * 72 + c8 * 8] = *(const uint4*)&g_vlo[goff];
        }
        __syncthreads();
        #pragma unroll
        for (int p = 0; p < 3; p++) {
            const __nv_bfloat16* aS = (p == 2) ? Pl : Ph;
            const __nv_bfloat16* bS = (p == 1) ? Vl : Vh;
            #pragma unroll
            for (int kk = 0; kk < 4; kk++) {
                wmma::fragment<wmma::matrix_a, 16, 16, 16, __nv_bfloat16, wmma::row_major> a;
                wmma::load_matrix_sync(a, aS + (wy * 16) * 72 + kk * 16, 72);
                #pragma unroll
                for (int j = 0; j < 2; j++) {
                    wmma::fragment<wmma::matrix_b, 16, 16, 16, __nv_bfloat16, wmma::row_major> b;
                    wmma::load_matrix_sync(b, bS + (kk * 16) * 72 + wx * 32 + j * 16, 72);
                    wmma::mma_sync(acc[j], a, b, acc[j]);
                }
            }
        }
        __syncthreads();
    }

    float tot = rowsum + __shfl_xor_sync(0xFFFFFFFFu, rowsum, 1);
    tot += __shfl_xor_sync(0xFFFFFFFFu, tot, 2);
    float inv = 1.0f / tot;
    if ((tid & 3) == 0) g_rowinv[(size_t)bh * SQ + s0 + row] = inv;

    wmma::store_matrix_sync(stage + (wy * 16) * 68 + wx * 32, acc[0], 68, wmma::mem_row_major);
    wmma::store_matrix_sync(stage + (wy * 16) * 68 + wx * 32 + 16, acc[1], 68, wmma::mem_row_major);
    __syncthreads();

    int b = bh >> 3, h = bh & 7;
    size_t obase = ((size_t)(s0 + row) * BB + b) * DD + h * HDIM + seg;
    #pragma unroll
    for (int j = 0; j < 4; j++) {
        float4 v = *(float4*)&stage[row * 68 + seg + j * 4];
        uint32_t h01, l01, h23, l23;
        split2(v.x * inv, v.y * inv, h01, l01);
        split2(v.z * inv, v.w * inv, h23, l23);
        *(uint2*)(g_cthi + obase + j * 4) = make_uint2(h01, h23);
        *(uint2*)(g_ctlo + obase + j * 4) = make_uint2(l01, l23);
    }
}

// ---------------------------------------------------------------------------
// K4: attn_weights[b,s,t] = mean_h exp(scores) * rowinv
// ---------------------------------------------------------------------------
__global__ void head_avg(float* __restrict__ out_attn) {
    size_t i = (size_t)blockIdx.x * blockDim.x + threadIdx.x;
    if (i >= (size_t)BB * SQ * SQ) return;
    size_t b   = i / ((size_t)SQ * SQ);
    size_t rem = i % ((size_t)SQ * SQ);
    size_t s   = rem / SQ;
    float sum = 0.0f;
    #pragma unroll
    for (int h = 0; h < HH; h++) {
        size_t bh = b * HH + h;
        sum += __expf(g_scores[bh * SQ * SQ + rem]) * g_rowinv[bh * SQ + s];
    }
    out_attn[i] = sum * 0.125f;
}

// ---------------------------------------------------------------------------
// K5: out = ctx @ out_w^T + out_b, split-bf16 3-product WMMA. CTA 64x64.
// ---------------------------------------------------------------------------
__global__ void __launch_bounds__(256) out_wmma(const float* __restrict__ bias,
                                                float* __restrict__ out) {
    __shared__ __align__(16) unsigned char smraw[36864];
    __nv_bfloat16* Ah = (__nv_bfloat16*)smraw;    // 64*72
    __nv_bfloat16* Al = Ah + 64 * 72;
    __nv_bfloat16* Bh = Al + 64 * 72;
    __nv_bfloat16* Bl = Bh + 64 * 72;
    float* stage = (float*)smraw;                 // 64*68

    int tid = threadIdx.x;
    int wid = tid >> 5;
    int wy = wid & 3, wx = wid >> 2;
    int n0 = blockIdx.x * 64, m0 = blockIdx.y * 64;

    wmma::fragment<wmma::accumulator, 16, 16, 16, float> acc[2];
    wmma::fill_fragment(acc[0], 0.0f);
    wmma::fill_fragment(acc[1], 0.0f);

    for (int k0 = 0; k0 < DD; k0 += 64) {
        #pragma unroll
        for (int l = 0; l < 2; l++) {
            int idx = tid + l * 256;
            int r = idx >> 3, c = idx & 7;
            *(uint4*)&Ah[r * 72 + c * 8] = *(const uint4*)&g_cthi[(size_t)(m0 + r) * DD + k0 + c * 8];
            *(uint4*)&Al[r * 72 + c * 8] = *(const uint4*)&g_ctlo[(size_t)(m0 + r) * DD + k0 + c * 8];
            *(uint4*)&Bh[r * 72 + c * 8] = *(const uint4*)&g_wohi[(size_t)(n0 + r) * DD + k0 + c * 8];
            *(uint4*)&Bl[r * 72 + c * 8] = *(const uint4*)&g_wolo[(size_t)(n0 + r) * DD + k0 + c * 8];
        }
        __syncthreads();
        #pragma unroll
        for (int p = 0; p < 3; p++) {
            const __nv_bfloat16* aS = (p == 2) ? Al : Ah;
            const __nv_bfloat16* bS = (p == 1) ? Bl : Bh;
            #pragma unroll
            for (int kk = 0; kk < 4; kk++) {
                wmma::fragment<wmma::matrix_a, 16, 16, 16, __nv_bfloat16, wmma::row_major> a;
                wmma::load_matrix_sync(a, aS + (wy * 16) * 72 + kk * 16, 72);
                #pragma unroll
                for (int j = 0; j < 2; j++) {
                    wmma::fragment<wmma::matrix_b, 16, 16, 16, __nv_bfloat16, wmma::col_major> b;
                    wmma::load_matrix_sync(b, bS + (wx * 32 + j * 16) * 72 + kk * 16, 72);
                    wmma::mma_sync(acc[j], a, b, acc[j]);
                }
            }
        }
        __syncthreads();
    }
    wmma::store_matrix_sync(stage + (wy * 16) * 68 + wx * 32, acc[0], 68, wmma::mem_row_major);
    wmma::store_matrix_sync(stage + (wy * 16) * 68 + wx * 32 + 16, acc[1], 68, wmma::mem_row_major);
    __syncthreads();

    int row = tid >> 2, q = (tid & 3) * 16;
    #pragma unroll
    for (int j = 0; j < 4; j++) {
        float4 v = *(float4*)&stage[row * 68 + q + j * 4];
        int col = n0 + q + j * 4;
        v.x += bias[col]; v.y += bias[col + 1]; v.z += bias[col + 2]; v.w += bias[col + 3];
        *(float4*)&out[(size_t)(m0 + row) * DD + col] = v;
    }
}

extern "C" void kernel_launch(void* const* d_in, const int* in_sizes, int n_in,
                              void* d_out, int out_size) {
    const float* src   = (const float*)d_in[0];
    const float* in_w  = (const float*)d_in[1];
    const float* in_b  = (const float*)d_in[2];
    const float* out_w = (const float*)d_in[3];
    const float* out_b = (const float*)d_in[4];
    float* out      = (float*)d_out;
    float* attn_out = out + (size_t)SQ * BB * DD;

    __nv_bfloat16 *shi, *slo, *wihi, *wilo, *wohi, *wolo;
    cudaGetSymbolAddress((void**)&shi,  g_shi);
    cudaGetSymbolAddress((void**)&slo,  g_slo);
    cudaGetSymbolAddress((void**)&wihi, g_wihi);
    cudaGetSymbolAddress((void**)&wilo, g_wilo);
    cudaGetSymbolAddress((void**)&wohi, g_wohi);
    cudaGetSymbolAddress((void**)&wolo, g_wolo);

    int n4s = MROWS * DD / 4, n4i = 3 * DD * DD / 4, n4o = DD * DD / 4;
    split_f32<<<(n4s + 255) / 256, 256>>>(src,  shi,  slo,  n4s);
    split_f32<<<(n4i + 255) / 256, 256>>>(in_w, wihi, wilo, n4i);
    split_f32<<<(n4o + 255) / 256, 256>>>(out_w, wohi, wolo, n4o);

    qkv_wmma<<<dim3(3 * DD / 64, MROWS / 128), 256>>>(in_b);
    scores_wmma<<<dim3(SQ / 64, SQ / 64, BH), 256>>>();
    ctx_wmma<<<dim3(SQ / 64, BH), 256>>>();
    head_avg<<<(unsigned)(((size_t)BB * SQ * SQ + 255) / 256), 256>>>(attn_out);
    out_wmma<<<dim3(DD / 64, MROWS / 64), 256>>>(out_b, out);
}

// round 6
// speedup vs baseline: 2.4265x; 1.0487x over previous
#include <cuda_runtime.h>
#include <cuda_bf16.h>
#include <mma.h>
#include <cstdint>

using namespace nvcuda;

#define SQ   2048
#define BB   8
#define DD   512
#define HH   8
#define HDIM 64
#define MROWS (SQ*BB)       // 16384
#define BH    (BB*HH)       // 64
#define STRD 72             // smem row stride (elems): 144B, 16B-aligned, conflict-free

// ---------------- scratch (__device__ globals) -----------------------------
__device__ __nv_bfloat16 g_shi[(size_t)MROWS*DD];
__device__ __nv_bfloat16 g_slo[(size_t)MROWS*DD];
__device__ __nv_bfloat16 g_wihi[(size_t)3*DD*DD];
__device__ __nv_bfloat16 g_wilo[(size_t)3*DD*DD];
__device__ __nv_bfloat16 g_wohi[(size_t)DD*DD];
__device__ __nv_bfloat16 g_wolo[(size_t)DD*DD];
__device__ __nv_bfloat16 g_qhi[(size_t)BH*SQ*HDIM];
__device__ __nv_bfloat16 g_qlo[(size_t)BH*SQ*HDIM];
__device__ __nv_bfloat16 g_khi[(size_t)BH*SQ*HDIM];
__device__ __nv_bfloat16 g_klo[(size_t)BH*SQ*HDIM];
__device__ __nv_bfloat16 g_vhi[(size_t)BH*SQ*HDIM];
__device__ __nv_bfloat16 g_vlo[(size_t)BH*SQ*HDIM];
__device__ float g_scores[(size_t)BH*SQ*SQ];
__device__ float g_rowinv[(size_t)BH*SQ];
__device__ __nv_bfloat16 g_cthi[(size_t)MROWS*DD];
__device__ __nv_bfloat16 g_ctlo[(size_t)MROWS*DD];

__device__ __forceinline__ void split2(float x0, float x1, uint32_t& hi, uint32_t& lo) {
    __nv_bfloat16 h0 = __float2bfloat16(x0), h1 = __float2bfloat16(x1);
    float r0 = x0 - __bfloat162float(h0), r1 = x1 - __bfloat162float(h1);
    __nv_bfloat162 H = __halves2bfloat162(h0, h1);
    __nv_bfloat162 L = __halves2bfloat162(__float2bfloat16(r0), __float2bfloat16(r1));
    hi = *(uint32_t*)&H;
    lo = *(uint32_t*)&L;
}

__device__ __forceinline__ uint32_t smem_u32(const void* p) {
    uint32_t a;
    asm("{ .reg .u64 t; cvta.to.shared.u64 t, %1; cvt.u32.u64 %0, t; }" : "=r"(a) : "l"(p));
    return a;
}
__device__ __forceinline__ void cpa16(uint32_t dst, const void* src) {
    asm volatile("cp.async.cg.shared.global [%0], [%1], 16;" :: "r"(dst), "l"(src));
}
#define CP_COMMIT asm volatile("cp.async.commit_group;" ::: "memory")
#define CP_WAIT0  asm volatile("cp.async.wait_group 0;" ::: "memory")
#define CP_WAIT1  asm volatile("cp.async.wait_group 1;" ::: "memory")

// ---------------------------------------------------------------------------
// K0: elementwise fp32 -> split bf16
// ---------------------------------------------------------------------------
__global__ void split_f32(const float* __restrict__ in, __nv_bfloat16* __restrict__ hi,
                          __nv_bfloat16* __restrict__ lo, int n4) {
    int i = blockIdx.x * blockDim.x + threadIdx.x;
    if (i >= n4) return;
    float4 v = ((const float4*)in)[i];
    uint32_t h01, l01, h23, l23;
    split2(v.x, v.y, h01, l01);
    split2(v.z, v.w, h23, l23);
    ((uint2*)hi)[i] = make_uint2(h01, h23);
    ((uint2*)lo)[i] = make_uint2(l01, l23);
}

// ---------------------------------------------------------------------------
// K1: QKV projection, split-bf16 3-product WMMA, 2-stage cp.async pipeline.
// CTA 128(m) x 64(n), K=512 in chunks of 64. Scatters split q/k/v.
// smem/stage: Ah/Al 128x72, Bh/Bl 64x72 -> 27648 elems; 2 stages = 108KB.
// ---------------------------------------------------------------------------
#define QKV_STG 27648
__global__ void __launch_bounds__(256) qkv_wmma(const float* __restrict__ bias) {
    extern __shared__ __align__(16) unsigned char dynsm[];
    __nv_bfloat16* sm = (__nv_bfloat16*)dynsm;
    uint32_t smb = smem_u32(dynsm);

    int tid = threadIdx.x;
    int wid = tid >> 5;
    int wy = wid & 3, wx = wid >> 2;
    int n0 = blockIdx.x * 64, m0 = blockIdx.y * 128;

    wmma::fragment<wmma::accumulator, 16, 16, 16, float> acc[2][2];
    #pragma unroll
    for (int i = 0; i < 2; i++)
        #pragma unroll
        for (int j = 0; j < 2; j++) wmma::fill_fragment(acc[i][j], 0.0f);

    auto load_stage = [&](int st, int k0) {
        uint32_t base = smb + st * QKV_STG * 2;
        #pragma unroll
        for (int l = 0; l < 4; l++) {
            int idx = tid + l * 256;
            int r = idx >> 3, c = idx & 7;
            size_t g = (size_t)(m0 + r) * DD + k0 + c * 8;
            uint32_t d = base + (r * STRD + c * 8) * 2;
            cpa16(d, &g_shi[g]);
            cpa16(d + 9216 * 2, &g_slo[g]);
        }
        #pragma unroll
        for (int l = 0; l < 2; l++) {
            int idx = tid + l * 256;
            int r = idx >> 3, c = idx & 7;
            size_t g = (size_t)(n0 + r) * DD + k0 + c * 8;
            uint32_t d = base + (18432 + r * STRD + c * 8) * 2;
            cpa16(d, &g_wihi[g]);
            cpa16(d + 4608 * 2, &g_wilo[g]);
        }
        CP_COMMIT;
    };

    load_stage(0, 0);
    for (int kt = 0; kt < 8; kt++) {
        if (kt + 1 < 8) { load_stage((kt + 1) & 1, (kt + 1) * 64); CP_WAIT1; }
        else CP_WAIT0;
        __syncthreads();
        const __nv_bfloat16* Ah = sm + (kt & 1) * QKV_STG;
        const __nv_bfloat16* Al = Ah + 9216;
        const __nv_bfloat16* Bh = Ah + 18432;
        const __nv_bfloat16* Bl = Ah + 23040;
        #pragma unroll
        for (int p = 0; p < 3; p++) {
            const __nv_bfloat16* aS = (p == 2) ? Al : Ah;
            const __nv_bfloat16* bS = (p == 1) ? Bl : Bh;
            #pragma unroll
            for (int kk = 0; kk < 4; kk++) {
                wmma::fragment<wmma::matrix_a, 16, 16, 16, __nv_bfloat16, wmma::row_major> a[2];
                wmma::fragment<wmma::matrix_b, 16, 16, 16, __nv_bfloat16, wmma::col_major> b[2];
                #pragma unroll
                for (int i = 0; i < 2; i++)
                    wmma::load_matrix_sync(a[i], aS + (wy * 32 + i * 16) * STRD + kk * 16, STRD);
                #pragma unroll
                for (int j = 0; j < 2; j++)
                    wmma::load_matrix_sync(b[j], bS + (wx * 32 + j * 16) * STRD + kk * 16, STRD);
                #pragma unroll
                for (int i = 0; i < 2; i++)
                    #pragma unroll
                    for (int j = 0; j < 2; j++)
                        wmma::mma_sync(acc[i][j], a[i], b[j], acc[i][j]);
            }
        }
        __syncthreads();
    }

    float* stage = (float*)dynsm;    // 128 x 68
    #pragma unroll
    for (int i = 0; i < 2; i++)
        #pragma unroll
        for (int j = 0; j < 2; j++)
            wmma::store_matrix_sync(stage + (wy * 32 + i * 16) * 68 + wx * 32 + j * 16,
                                    acc[i][j], 68, wmma::mem_row_major);
    __syncthreads();

    int row = tid >> 1, half = (tid & 1) * 32;
    int part = n0 >> 9;
    int h = (n0 >> 6) & 7;
    int i = m0 + row;
    int s = i >> 3, b = i & 7;
    int bh = b * HH + h;
    float scale = (part == 0) ? 0.125f : 1.0f;
    size_t obase = ((size_t)bh * SQ + s) * HDIM + half;
    __nv_bfloat16* ph = (part == 0) ? g_qhi : (part == 1) ? g_khi : g_vhi;
    __nv_bfloat16* pl = (part == 0) ? g_qlo : (part == 1) ? g_klo : g_vlo;
    #pragma unroll
    for (int j = 0; j < 8; j++) {
        float4 v = *(float4*)&stage[row * 68 + half + j * 4];
        int col = n0 + half + j * 4;
        v.x = (v.x + bias[col]) * scale;
        v.y = (v.y + bias[col + 1]) * scale;
        v.z = (v.z + bias[col + 2]) * scale;
        v.w = (v.w + bias[col + 3]) * scale;
        uint32_t h01, l01, h23, l23;
        split2(v.x, v.y, h01, l01);
        split2(v.z, v.w, h23, l23);
        *(uint2*)(ph + obase + j * 4) = make_uint2(h01, h23);
        *(uint2*)(pl + obase + j * 4) = make_uint2(l01, l23);
    }
}

// ---------------------------------------------------------------------------
// K2: scores = Q.K^T, split-bf16 3-product WMMA. CTA 128(s) x 64(t), K=64.
// Single-shot cp.async load. smem 27648 elems = 54KB.
// ---------------------------------------------------------------------------
__global__ void __launch_bounds__(256) scores_wmma() {
    extern __shared__ __align__(16) unsigned char dynsm[];
    __nv_bfloat16* sm = (__nv_bfloat16*)dynsm;
    uint32_t smb = smem_u32(dynsm);

    int tid = threadIdx.x;
    int wid = tid >> 5;
    int wy = wid & 3, wx = wid >> 2;
    int bh = blockIdx.z;
    int s0 = blockIdx.y * 128;
    int t0 = blockIdx.x * 64;

    // Qh 0, Ql 9216, Kh 18432, Kl 23040
    #pragma unroll
    for (int l = 0; l < 4; l++) {
        int idx = tid + l * 256;
        int r = idx >> 3, c = idx & 7;
        size_t g = ((size_t)bh * SQ + s0 + r) * HDIM + c * 8;
        uint32_t d = smb + (r * STRD + c * 8) * 2;
        cpa16(d, &g_qhi[g]);
        cpa16(d + 9216 * 2, &g_qlo[g]);
    }
    #pragma unroll
    for (int l = 0; l < 2; l++) {
        int idx = tid + l * 256;
        int r = idx >> 3, c = idx & 7;
        size_t g = ((size_t)bh * SQ + t0 + r) * HDIM + c * 8;
        uint32_t d = smb + (18432 + r * STRD + c * 8) * 2;
        cpa16(d, &g_khi[g]);
        cpa16(d + 4608 * 2, &g_klo[g]);
    }
    CP_COMMIT;
    CP_WAIT0;
    __syncthreads();

    const __nv_bfloat16* Qh = sm;
    const __nv_bfloat16* Ql = sm + 9216;
    const __nv_bfloat16* Kh = sm + 18432;
    const __nv_bfloat16* Kl = sm + 23040;

    wmma::fragment<wmma::accumulator, 16, 16, 16, float> acc[2][2];
    #pragma unroll
    for (int i = 0; i < 2; i++)
        #pragma unroll
        for (int j = 0; j < 2; j++) wmma::fill_fragment(acc[i][j], 0.0f);

    #pragma unroll
    for (int p = 0; p < 3; p++) {
        const __nv_bfloat16* aS = (p == 2) ? Ql : Qh;
        const __nv_bfloat16* bS = (p == 1) ? Kl : Kh;
        #pragma unroll
        for (int kk = 0; kk < 4; kk++) {
            wmma::fragment<wmma::matrix_a, 16, 16, 16, __nv_bfloat16, wmma::row_major> a[2];
            wmma::fragment<wmma::matrix_b, 16, 16, 16, __nv_bfloat16, wmma::col_major> b[2];
            #pragma unroll
            for (int i = 0; i < 2; i++)
                wmma::load_matrix_sync(a[i], aS + (wy * 32 + i * 16) * STRD + kk * 16, STRD);
            #pragma unroll
            for (int j = 0; j < 2; j++)
                wmma::load_matrix_sync(b[j], bS + (wx * 32 + j * 16) * STRD + kk * 16, STRD);
            #pragma unroll
            for (int i = 0; i < 2; i++)
                #pragma unroll
                for (int j = 0; j < 2; j++)
                    wmma::mma_sync(acc[i][j], a[i], b[j], acc[i][j]);
        }
    }
    #pragma unroll
    for (int i = 0; i < 2; i++)
        #pragma unroll
        for (int j = 0; j < 2; j++) {
            float* out = g_scores + ((size_t)bh * SQ + s0 + wy * 32 + i * 16) * SQ + t0 + wx * 32 + j * 16;
            wmma::store_matrix_sync(out, acc[i][j], SQ, wmma::mem_row_major);
        }
}

// ---------------------------------------------------------------------------
// K3: ctx = exp(scores) @ V, split-bf16 3-product WMMA; rowsum fused.
// CTA 128(s) x 64(d), K=2048 in 64-chunks; P ping-pong + V cp.async 2-stage.
// smem: Ph2 2x9216, Pl2 2x9216, Vh2 2x4608, Vl2 2x4608 = 55296 elems = 108KB.
// ---------------------------------------------------------------------------
__global__ void __launch_bounds__(256) ctx_wmma() {
    extern __shared__ __align__(16) unsigned char dynsm[];
    __nv_bfloat16* sm = (__nv_bfloat16*)dynsm;
    uint32_t smb = smem_u32(dynsm);

    int tid = threadIdx.x;
    int wid = tid >> 5;
    int wy = wid & 3, wx = wid >> 2;
    int bh = blockIdx.y;
    int s0 = blockIdx.x * 128;

    int row = tid >> 1, half = (tid & 1) * 32;
    const float* prow = g_scores + ((size_t)bh * SQ + s0 + row) * SQ + half;

    auto load_v = [&](int st, int c) {
        #pragma unroll
        for (int l = 0; l < 2; l++) {
            int idx = tid + l * 256;
            int r = idx >> 3, c8 = idx & 7;
            size_t g = ((size_t)bh * SQ + c * 64 + r) * HDIM + c8 * 8;
            uint32_t d = smb + (36864 + st * 4608 + r * STRD + c8 * 8) * 2;
            cpa16(d, &g_vhi[g]);
            cpa16(d + 9216 * 2, &g_vlo[g]);
        }
        CP_COMMIT;
    };

    wmma::fragment<wmma::accumulator, 16, 16, 16, float> acc[2][2];
    #pragma unroll
    for (int i = 0; i < 2; i++)
        #pragma unroll
        for (int j = 0; j < 2; j++) wmma::fill_fragment(acc[i][j], 0.0f);

    float4 cur[8];
    #pragma unroll
    for (int j = 0; j < 8; j++) cur[j] = *(const float4*)&prow[j * 4];
    load_v(0, 0);

    float rowsum = 0.0f;
    for (int c = 0; c < 32; c++) {
        int st = c & 1;
        if (c + 1 < 32) load_v((c + 1) & 1, c + 1);
        // exp + split current chunk into P stage st
        __nv_bfloat16* Ph = sm + st * 9216;
        __nv_bfloat16* Pl = sm + 18432 + st * 9216;
        #pragma unroll
        for (int j = 0; j < 8; j++) {
            float e0 = __expf(cur[j].x), e1 = __expf(cur[j].y);
            float e2 = __expf(cur[j].z), e3 = __expf(cur[j].w);
            rowsum += (e0 + e1) + (e2 + e3);
            uint32_t h01, l01, h23, l23;
            split2(e0, e1, h01, l01);
            split2(e2, e3, h23, l23);
            *(uint2*)&Ph[row * STRD + half + j * 4] = make_uint2(h01, h23);
            *(uint2*)&Pl[row * STRD + half + j * 4] = make_uint2(l01, l23);
        }
        if (c + 1 < 32) {
            #pragma unroll
            for (int j = 0; j < 8; j++) cur[j] = *(const float4*)&prow[(c + 1) * 64 + j * 4];
            CP_WAIT1;
        } else CP_WAIT0;
        __syncthreads();
        const __nv_bfloat16* Vh = sm + 36864 + st * 4608;
        const __nv_bfloat16* Vl = sm + 46080 + st * 4608;
        #pragma unroll
        for (int p = 0; p < 3; p++) {
            const __nv_bfloat16* aS = (p == 2) ? Pl : Ph;
            const __nv_bfloat16* bS = (p == 1) ? Vl : Vh;
            #pragma unroll
            for (int kk = 0; kk < 4; kk++) {
                wmma::fragment<wmma::matrix_a, 16, 16, 16, __nv_bfloat16, wmma::row_major> a[2];
                wmma::fragment<wmma::matrix_b, 16, 16, 16, __nv_bfloat16, wmma::row_major> b[2];
                #pragma unroll
                for (int i = 0; i < 2; i++)
                    wmma::load_matrix_sync(a[i], aS + (wy * 32 + i * 16) * STRD + kk * 16, STRD);
                #pragma unroll
                for (int j = 0; j < 2; j++)
                    wmma::load_matrix_sync(b[j], bS + (kk * 16) * STRD + wx * 32 + j * 16, STRD);
                #pragma unroll
                for (int i = 0; i < 2; i++)
                    #pragma unroll
                    for (int j = 0; j < 2; j++)
                        wmma::mma_sync(acc[i][j], a[i], b[j], acc[i][j]);
            }
        }
        __syncthreads();
    }

    float tot = rowsum + __shfl_xor_sync(0xFFFFFFFFu, rowsum, 1);
    float inv = 1.0f / tot;
    if (!(tid & 1)) g_rowinv[(size_t)bh * SQ + s0 + row] = inv;

    float* stage = (float*)dynsm;   // 128 x 68
    __syncthreads();
    #pragma unroll
    for (int i = 0; i < 2; i++)
        #pragma unroll
        for (int j = 0; j < 2; j++)
            wmma::store_matrix_sync(stage + (wy * 32 + i * 16) * 68 + wx * 32 + j * 16,
                                    acc[i][j], 68, wmma::mem_row_major);
    __syncthreads();

    int b = bh >> 3, h = bh & 7;
    size_t obase = ((size_t)(s0 + row) * BB + b) * DD + h * HDIM + half;
    #pragma unroll
    for (int j = 0; j < 8; j++) {
        float4 v = *(float4*)&stage[row * 68 + half + j * 4];
        uint32_t h01, l01, h23, l23;
        split2(v.x * inv, v.y * inv, h01, l01);
        split2(v.z * inv, v.w * inv, h23, l23);
        *(uint2*)(g_cthi + obase + j * 4) = make_uint2(h01, h23);
        *(uint2*)(g_ctlo + obase + j * 4) = make_uint2(l01, l23);
    }
}

// ---------------------------------------------------------------------------
// K4: attn_weights[b,s,t] = mean_h exp(scores) * rowinv
// ---------------------------------------------------------------------------
__global__ void head_avg(float* __restrict__ out_attn) {
    size_t i = (size_t)blockIdx.x * blockDim.x + threadIdx.x;
    if (i >= (size_t)BB * SQ * SQ) return;
    size_t b   = i / ((size_t)SQ * SQ);
    size_t rem = i % ((size_t)SQ * SQ);
    size_t s   = rem / SQ;
    float sum = 0.0f;
    #pragma unroll
    for (int h = 0; h < HH; h++) {
        size_t bh = b * HH + h;
        sum += __expf(g_scores[bh * SQ * SQ + rem]) * g_rowinv[bh * SQ + s];
    }
    out_attn[i] = sum * 0.125f;
}

// ---------------------------------------------------------------------------
// K5: out = ctx @ out_w^T + out_b, split-bf16 3-product WMMA, pipelined.
// CTA 128(m) x 64(n), K=512 chunks of 64. Same smem layout as qkv.
// ---------------------------------------------------------------------------
__global__ void __launch_bounds__(256) out_wmma(const float* __restrict__ bias,
                                                float* __restrict__ out) {
    extern __shared__ __align__(16) unsigned char dynsm[];
    __nv_bfloat16* sm = (__nv_bfloat16*)dynsm;
    uint32_t smb = smem_u32(dynsm);

    int tid = threadIdx.x;
    int wid = tid >> 5;
    int wy = wid & 3, wx = wid >> 2;
    int n0 = blockIdx.x * 64, m0 = blockIdx.y * 128;

    wmma::fragment<wmma::accumulator, 16, 16, 16, float> acc[2][2];
    #pragma unroll
    for (int i = 0; i < 2; i++)
        #pragma unroll
        for (int j = 0; j < 2; j++) wmma::fill_fragment(acc[i][j], 0.0f);

    auto load_stage = [&](int st, int k0) {
        uint32_t base = smb + st * QKV_STG * 2;
        #pragma unroll
        for (int l = 0; l < 4; l++) {
            int idx = tid + l * 256;
            int r = idx >> 3, c = idx & 7;
            size_t g = (size_t)(m0 + r) * DD + k0 + c * 8;
            uint32_t d = base + (r * STRD + c * 8) * 2;
            cpa16(d, &g_cthi[g]);
            cpa16(d + 9216 * 2, &g_ctlo[g]);
        }
        #pragma unroll
        for (int l = 0; l < 2; l++) {
            int idx = tid + l * 256;
            int r = idx >> 3, c = idx & 7;
            size_t g = (size_t)(n0 + r) * DD + k0 + c * 8;
            uint32_t d = base + (18432 + r * STRD + c * 8) * 2;
            cpa16(d, &g_wohi[g]);
            cpa16(d + 4608 * 2, &g_wolo[g]);
        }
        CP_COMMIT;
    };

    load_stage(0, 0);
    for (int kt = 0; kt < 8; kt++) {
        if (kt + 1 < 8) { load_stage((kt + 1) & 1, (kt + 1) * 64); CP_WAIT1; }
        else CP_WAIT0;
        __syncthreads();
        const __nv_bfloat16* Ah = sm + (kt & 1) * QKV_STG;
        const __nv_bfloat16* Al = Ah + 9216;
        const __nv_bfloat16* Bh = Ah + 18432;
        const __nv_bfloat16* Bl = Ah + 23040;
        #pragma unroll
        for (int p = 0; p < 3; p++) {
            const __nv_bfloat16* aS = (p == 2) ? Al : Ah;
            const __nv_bfloat16* bS = (p == 1) ? Bl : Bh;
            #pragma unroll
            for (int kk = 0; kk < 4; kk++) {
                wmma::fragment<wmma::matrix_a, 16, 16, 16, __nv_bfloat16, wmma::row_major> a[2];
                wmma::fragment<wmma::matrix_b, 16, 16, 16, __nv_bfloat16, wmma::col_major> b[2];
                #pragma unroll
                for (int i = 0; i < 2; i++)
                    wmma::load_matrix_sync(a[i], aS + (wy * 32 + i * 16) * STRD + kk * 16, STRD);
                #pragma unroll
                for (int j = 0; j < 2; j++)
                    wmma::load_matrix_sync(b[j], bS + (wx * 32 + j * 16) * STRD + kk * 16, STRD);
                #pragma unroll
                for (int i = 0; i < 2; i++)
                    #pragma unroll
                    for (int j = 0; j < 2; j++)
                        wmma::mma_sync(acc[i][j], a[i], b[j], acc[i][j]);
            }
        }
        __syncthreads();
    }

    float* stage = (float*)dynsm;    // 128 x 68
    #pragma unroll
    for (int i = 0; i < 2; i++)
        #pragma unroll
        for (int j = 0; j < 2; j++)
            wmma::store_matrix_sync(stage + (wy * 32 + i * 16) * 68 + wx * 32 + j * 16,
                                    acc[i][j], 68, wmma::mem_row_major);
    __syncthreads();

    int row = tid >> 1, half = (tid & 1) * 32;
    #pragma unroll
    for (int j = 0; j < 8; j++) {
        float4 v = *(float4*)&stage[row * 68 + half + j * 4];
        int col = n0 + half + j * 4;
        v.x += bias[col]; v.y += bias[col + 1]; v.z += bias[col + 2]; v.w += bias[col + 3];
        *(float4*)&out[(size_t)(m0 + row) * DD + col] = v;
    }
}

extern "C" void kernel_launch(void* const* d_in, const int* in_sizes, int n_in,
                              void* d_out, int out_size) {
    const float* src   = (const float*)d_in[0];
    const float* in_w  = (const float*)d_in[1];
    const float* in_b  = (const float*)d_in[2];
    const float* out_w = (const float*)d_in[3];
    const float* out_b = (const float*)d_in[4];
    float* out      = (float*)d_out;
    float* attn_out = out + (size_t)SQ * BB * DD;

    __nv_bfloat16 *shi, *slo, *wihi, *wilo, *wohi, *wolo;
    cudaGetSymbolAddress((void**)&shi,  g_shi);
    cudaGetSymbolAddress((void**)&slo,  g_slo);
    cudaGetSymbolAddress((void**)&wihi, g_wihi);
    cudaGetSymbolAddress((void**)&wilo, g_wilo);
    cudaGetSymbolAddress((void**)&wohi, g_wohi);
    cudaGetSymbolAddress((void**)&wolo, g_wolo);

    const int SM_BIG   = 2 * QKV_STG * 2;   // 110592
    const int SM_SCORE = 27648 * 2;         // 55296
    cudaFuncSetAttribute(qkv_wmma,    cudaFuncAttributeMaxDynamicSharedMemorySize, SM_BIG);
    cudaFuncSetAttribute(ctx_wmma,    cudaFuncAttributeMaxDynamicSharedMemorySize, SM_BIG);
    cudaFuncSetAttribute(out_wmma,    cudaFuncAttributeMaxDynamicSharedMemorySize, SM_BIG);
    cudaFuncSetAttribute(scores_wmma, cudaFuncAttributeMaxDynamicSharedMemorySize, SM_SCORE);

    int n4s = MROWS * DD / 4, n4i = 3 * DD * DD / 4, n4o = DD * DD / 4;
    split_f32<<<(n4s + 255) / 256, 256>>>(src,  shi,  slo,  n4s);
    split_f32<<<(n4i + 255) / 256, 256>>>(in_w, wihi, wilo, n4i);
    split_f32<<<(n4o + 255) / 256, 256>>>(out_w, wohi, wolo, n4o);

    qkv_wmma<<<dim3(3 * DD / 64, MROWS / 128), 256, SM_BIG>>>(in_b);
    scores_wmma<<<dim3(SQ / 64, SQ / 128, BH), 256, SM_SCORE>>>();
    ctx_wmma<<<dim3(SQ / 128, BH), 256, SM_BIG>>>();
    head_avg<<<(unsigned)(((size_t)BB * SQ * SQ + 255) / 256), 256>>>(attn_out);
    out_wmma<<<dim3(DD / 64, MROWS / 128), 256, SM_BIG>>>(out_b, out);
}